// round 1
// baseline (speedup 1.0000x reference)
#include <cuda_runtime.h>

#define BATCH 16
#define NV    20000
#define FIN   64
#define COUT  64
#define KNB   16
#define TILE_V 64
#define PAD    65   // smem row stride (floats): 65 -> 2-way max bank conflict on scalar reads

__constant__ float cWx[FIN * COUT];   // [f][c]
__constant__ float cWn[FIN * COUT];   // [f][c]
__constant__ float cBias[COUT];

__global__ __launch_bounds__(256)
void convnet_fused_kernel(const float* __restrict__ x,
                          const int*   __restrict__ neighbor,
                          float*       __restrict__ out)
{
    __shared__ float sX[TILE_V * PAD];   // x tile, [v][f]
    __shared__ float sN[TILE_V * PAD];   // neighbor-mean tile, [v][f]

    const int b   = blockIdx.y;
    const int v0  = blockIdx.x * TILE_V;
    const int tid = threadIdx.x;
    const float* __restrict__ xb = x + (size_t)b * NV * FIN;

    // ---------------- Phase 1: load x tile (coalesced float4 reads) --------
    #pragma unroll
    for (int it = 0; it < 4; ++it) {
        int linear = tid + it * 256;          // 0..1023 covers 64 rows * 16 float4
        int vi = linear >> 4;
        int fq = linear & 15;
        int v  = v0 + vi;
        float4 val = make_float4(0.f, 0.f, 0.f, 0.f);
        if (v < NV)
            val = *(const float4*)(xb + (size_t)v * FIN + fq * 4);
        float* dst = &sX[vi * PAD + fq * 4];
        dst[0] = val.x; dst[1] = val.y; dst[2] = val.z; dst[3] = val.w;
    }

    // ---------------- Phase 2: gather + mean (half-warp per vertex) --------
    // Each gathered row is 64 floats = 16 lanes * float4 (256B, 2 cache lines).
    const int hw  = tid >> 4;   // half-warp id 0..15
    const int l16 = tid & 15;   // lane within half-warp
    for (int vi = hw; vi < TILE_V; vi += 16) {
        const int v = v0 + vi;
        int nid = 0;
        if (v < NV)
            nid = __ldg(&neighbor[v * KNB + l16]);   // lane l16 holds neighbor k=l16

        float4 acc = make_float4(0.f, 0.f, 0.f, 0.f);
        #pragma unroll
        for (int k = 0; k < KNB; ++k) {
            int r = __shfl_sync(0xffffffffu, nid, k, 16);  // broadcast within half-warp
            if (r > 0) {   // r==0 is the zero-pad row
                float4 t = *(const float4*)(xb + (size_t)(r - 1) * FIN + l16 * 4);
                acc.x += t.x; acc.y += t.y; acc.z += t.z; acc.w += t.w;
            }
        }
        const float s = 1.0f / (float)KNB;
        float* dst = &sN[vi * PAD + l16 * 4];
        dst[0] = acc.x * s; dst[1] = acc.y * s; dst[2] = acc.z * s; dst[3] = acc.w * s;
    }
    __syncthreads();

    // ---------------- Phase 3: dual micro-GEMM, 4 verts x 4 chans / thread -
    const int vg = tid & 15;   // vertex group: verts vg*4 .. vg*4+3
    const int cg = tid >> 4;   // channel group: chans cg*4 .. cg*4+3
    float4 acc0, acc1, acc2, acc3;
    {
        const float4 bias = *(const float4*)&cBias[cg * 4];
        acc0 = bias; acc1 = bias; acc2 = bias; acc3 = bias;
    }

    #pragma unroll 4
    for (int f = 0; f < FIN; ++f) {
        const float4 wx = *(const float4*)&cWx[f * COUT + cg * 4];
        const float4 wn = *(const float4*)&cWn[f * COUT + cg * 4];
        const int base = vg * 4 * PAD + f;
        float x0 = sX[base + 0 * PAD], n0 = sN[base + 0 * PAD];
        float x1 = sX[base + 1 * PAD], n1 = sN[base + 1 * PAD];
        float x2 = sX[base + 2 * PAD], n2 = sN[base + 2 * PAD];
        float x3 = sX[base + 3 * PAD], n3 = sN[base + 3 * PAD];

        acc0.x += x0 * wx.x + n0 * wn.x;  acc0.y += x0 * wx.y + n0 * wn.y;
        acc0.z += x0 * wx.z + n0 * wn.z;  acc0.w += x0 * wx.w + n0 * wn.w;
        acc1.x += x1 * wx.x + n1 * wn.x;  acc1.y += x1 * wx.y + n1 * wn.y;
        acc1.z += x1 * wx.z + n1 * wn.z;  acc1.w += x1 * wx.w + n1 * wn.w;
        acc2.x += x2 * wx.x + n2 * wn.x;  acc2.y += x2 * wx.y + n2 * wn.y;
        acc2.z += x2 * wx.z + n2 * wn.z;  acc2.w += x2 * wx.w + n2 * wn.w;
        acc3.x += x3 * wx.x + n3 * wn.x;  acc3.y += x3 * wx.y + n3 * wn.y;
        acc3.z += x3 * wx.z + n3 * wn.z;  acc3.w += x3 * wx.w + n3 * wn.w;
    }

    // ---------------- Phase 4: store ---------------------------------------
    float* __restrict__ outb = out + (size_t)b * NV * COUT;
    {
        int v = v0 + vg * 4 + 0;
        if (v < NV) *(float4*)(outb + (size_t)v * COUT + cg * 4) = acc0;
        v = v0 + vg * 4 + 1;
        if (v < NV) *(float4*)(outb + (size_t)v * COUT + cg * 4) = acc1;
        v = v0 + vg * 4 + 2;
        if (v < NV) *(float4*)(outb + (size_t)v * COUT + cg * 4) = acc2;
        v = v0 + vg * 4 + 3;
        if (v < NV) *(float4*)(outb + (size_t)v * COUT + cg * 4) = acc3;
    }
}

extern "C" void kernel_launch(void* const* d_in, const int* in_sizes, int n_in,
                              void* d_out, int out_size)
{
    // metadata order: x, Wx, Wn, b, neighbor
    const float* x        = (const float*)d_in[0];
    const void*  Wx       = d_in[1];
    const void*  Wn       = d_in[2];
    const void*  bias     = d_in[3];
    const int*   neighbor = (const int*)d_in[4];
    float*       out      = (float*)d_out;

    // D2D copies into constant memory: capturable as memcpy nodes.
    cudaMemcpyToSymbolAsync(cWx,   Wx,   FIN * COUT * sizeof(float), 0,
                            cudaMemcpyDeviceToDevice, 0);
    cudaMemcpyToSymbolAsync(cWn,   Wn,   FIN * COUT * sizeof(float), 0,
                            cudaMemcpyDeviceToDevice, 0);
    cudaMemcpyToSymbolAsync(cBias, bias, COUT * sizeof(float), 0,
                            cudaMemcpyDeviceToDevice, 0);

    dim3 grid((NV + TILE_V - 1) / TILE_V, BATCH);
    convnet_fused_kernel<<<grid, 256>>>(x, neighbor, out);
}